// round 5
// baseline (speedup 1.0000x reference)
#include <cuda_runtime.h>

#define B   8
#define CI  32
#define CO  32
#define NY  128
#define NX  128
#define M1  4
#define M2  5

#define TWO_PI_F 6.283185307179586476925f

typedef unsigned long long ull;

__device__ __forceinline__ float2 cmul(float2 a, float2 b) {
    return make_float2(a.x*b.x - a.y*b.y, a.x*b.y + a.y*b.x);
}
__device__ __forceinline__ float2 cfma(float2 a, float2 b, float2 c) {
    c.x = fmaf(a.x, b.x, fmaf(-a.y, b.y, c.x));
    c.y = fmaf(a.x, b.y, fmaf( a.y, b.x, c.y));
    return c;
}
__device__ __forceinline__ ull pack2(float lo, float hi) {
    ull r; asm("mov.b64 %0, {%1, %2};" : "=l"(r) : "f"(lo), "f"(hi)); return r;
}
__device__ __forceinline__ float2 unpack2(ull v) {
    float2 f; asm("mov.b64 {%0, %1}, %2;" : "=f"(f.x), "=f"(f.y) : "l"(v)); return f;
}
__device__ __forceinline__ ull fma2(ull a, ull b, ull c) {
    ull d; asm("fma.rn.f32x2 %0, %1, %2, %3;" : "=l"(d) : "l"(a), "l"(b), "l"(c)); return d;
}

// ---------------- scratch ---------------------------------------------------
__device__ float2 g_tmp  [B*CI*NY*NX];
__device__ float2 g_alpha[B*CI*NY*NX];
__device__ float2 g_A1   [CI*CO*M1*NY];
__device__ float2 g_A2   [CI*CO*M2*NX];
__device__ float2 g_E1   [CI*CO*M1*NY];
__device__ float2 g_E2   [CI*CO*M2*NX];
__device__ float2 g_H    [CI*CO*NY*NX];
__device__ float2 g_T2   [B*CI*CO*M2*NY];
__device__ float2 g_res2 [B*CO*M1*M2];
__device__ float2 g_G    [B*CI*CO*M2*NY];

// compute 64-entry twiddle table in shared memory (forward sign)
__device__ __forceinline__ void make_tws(float2* tws, int t) {
    if (t < 64) {
        float sn, cs;
        sincospif(-(float)t / 64.f, &sn, &cs);
        tws[t] = make_float2(cs, sn);
    }
}

// ---------------- merged pole factors (launch 0) ----------------------------
__global__ void k_fac(const float* __restrict__ wp1_re, const float* __restrict__ wp1_im,
                      const float* __restrict__ wp2_re, const float* __restrict__ wp2_im,
                      const float* __restrict__ ty, const float* __restrict__ tx) {
    int blk = blockIdx.x;
    int o   = threadIdx.x;
    if (blk < CI*CO*M1) {
        int ikp = blk;
        float wr = wp1_re[ikp], wi = wp1_im[ikp];
        float d = ty[1] - ty[0];
        float invnd = 1.0f / ((float)NY * d);
        float k = (o < NY/2) ? (float)o : (float)(o - NY);
        float lam = TWO_PI_F * k * invnd;
        float a = -wr, b = lam - wi;
        float inv = 1.0f / (a*a + b*b);
        g_A1[ikp*NY + o] = make_float2(a*inv, -b*inv);
        float t = ty[o];
        float e = expf(wr * t);
        float sn, cs; sincosf(wi * t, &sn, &cs);
        g_E1[ikp*NY + o] = make_float2(e*cs, e*sn);
    } else {
        int ikq = blk - CI*CO*M1;
        float wr = wp2_re[ikq], wi = wp2_im[ikq];
        float d = tx[1] - tx[0];
        float invnd = 1.0f / ((float)NX * d);
        float k = (o < NX/2) ? (float)o : (float)(o - NX);
        float lam = TWO_PI_F * k * invnd;
        float a = -wr, b = lam - wi;
        float inv = 1.0f / (a*a + b*b);
        g_A2[ikq*NX + o] = make_float2(a*inv, -b*inv);
        float t = tx[o];
        float e = expf(wr * t);
        float sn, cs; sincosf(wi * t, &sn, &cs);
        g_E2[ikq*NX + o] = make_float2(e*cs, e*sn);
    }
}

// ---------------- 128-pt radix-2 DIT, table twiddles ------------------------
template<int INV>
__device__ __forceinline__ void fft64th(float2* s, int tt, const float2* tws) {
    #pragma unroll
    for (int stage = 1; stage <= 7; stage++) {
        __syncthreads();
        int half = 1 << (stage - 1);
        int p  = tt & (half - 1);
        int i0 = ((tt >> (stage - 1)) << stage) + p;
        int i1 = i0 + half;
        float2 w = tws[p << (7 - stage)];
        float wy = INV ? -w.y : w.y;
        float2 u = s[i0], v0 = s[i1];
        float2 v = make_float2(v0.x*w.x - v0.y*wy, v0.x*wy + v0.y*w.x);
        s[i0] = make_float2(u.x + v.x, u.y + v.y);
        s[i1] = make_float2(u.x - v.x, u.y - v.y);
    }
}

// forward FFT of real rows (launch 1)
__global__ void k_fft_rows_f(const float* __restrict__ x) {
    __shared__ float2 s[2][NX];
    __shared__ float2 tws[64];
    int t = threadIdx.x, r = t >> 6, tt = t & 63;
    make_tws(tws, t);
    size_t row = (size_t)blockIdx.x * 2 + r;
    const float* xr = x + row * NX;
    s[r][tt]      = make_float2(xr[__brev(tt)      >> 25], 0.f);
    s[r][tt + 64] = make_float2(xr[__brev(tt + 64) >> 25], 0.f);
    fft64th<0>(s[r], tt, tws);
    float2* o = g_tmp + row * NX;
    o[tt] = s[r][tt]; o[tt + 64] = s[r][tt + 64];
}

template<int INV>
__device__ __forceinline__ void fft_col(float2 (*tile)[17], int tg, int tx, const float2* tws) {
    #pragma unroll
    for (int stage = 1; stage <= 7; stage++) {
        __syncthreads();
        int half = 1 << (stage - 1);
        #pragma unroll
        for (int m = 0; m < 8; m++) {
            int j  = tg + 8 * m;
            int p  = j & (half - 1);
            int i0 = ((j >> (stage - 1)) << stage) + p;
            int i1 = i0 + half;
            float2 w = tws[p << (7 - stage)];
            float wy = INV ? -w.y : w.y;
            float2 u = tile[i0][tx], v0 = tile[i1][tx];
            float2 v = make_float2(v0.x*w.x - v0.y*wy, v0.x*wy + v0.y*w.x);
            tile[i0][tx] = make_float2(u.x + v.x, u.y + v.y);
            tile[i1][tx] = make_float2(u.x - v.x, u.y - v.y);
        }
    }
}

// forward columns (launch 2): g_tmp -> g_alpha
__global__ void k_fft_cols_f() {
    __shared__ float2 tile[NY][17];
    __shared__ float2 tws[64];
    int t = threadIdx.x;
    make_tws(tws, t);
    int blk = blockIdx.x;
    int xt = blk & 7, img = blk >> 3;
    int x0 = xt * 16;
    int tg = t >> 4, tx = t & 15;
    const float2* base = g_tmp + (size_t)img * NY * NX + x0;
    #pragma unroll
    for (int c = 0; c < 16; c++) {
        int y = c * 8 + tg;
        tile[__brev(y) >> 25][tx] = base[(size_t)y * NX + tx];
    }
    fft_col<0>(tile, tg, tx, tws);
    __syncthreads();
    float2* ob = g_alpha + (size_t)img * NY * NX + x0;
    #pragma unroll
    for (int c = 0; c < 16; c++) {
        int y = c * 8 + tg;
        ob[(size_t)y * NX + tx] = tile[y][tx];
    }
}

// ---------------- T2: packed-complex FFMA2 GEMM (launch 3 -> gets profiled) -
#define T2_CHUNK 40
#define T2_SMEM ((128*129 + T2_CHUNK*129) * sizeof(float2))
extern __shared__ float2 t2sm[];
__global__ void __launch_bounds__(256, 1) k_T2() {
    float2* alphaS = t2sm;
    float2* a2S    = t2sm + 128*129;
    int blk = blockIdx.x;
    int c  = blk & 3;
    int bi = blk >> 2;
    int i  = bi & 31;
    int kq0 = c * T2_CHUNK;
    int t = threadIdx.x;
    const float2* A = g_alpha + (size_t)bi * NY * NX;
    for (int l = t; l < 128*128; l += 256) {
        int o = l >> 7, x = l & 127;
        alphaS[o*129 + x] = A[(size_t)o * NX + x];
    }
    for (int l = t; l < T2_CHUNK*128; l += 256) {
        int r = l >> 7, x = l & 127;
        a2S[r*129 + x] = g_A2[(size_t)(i*CO*M2 + kq0 + r) * NX + x];
    }
    __syncthreads();
    int u = t >> 5, v = t & 31;
    ull acc[5][4];
    #pragma unroll
    for (int j = 0; j < 5; j++)
        #pragma unroll
        for (int m = 0; m < 4; m++) acc[j][m] = pack2(0.f, 0.f);
    #pragma unroll 2
    for (int x = 0; x < 128; x++) {
        ull bxx[5], bpm[5];
        #pragma unroll
        for (int j = 0; j < 5; j++) {
            float2 b = a2S[(u*5 + j)*129 + x];
            bxx[j] = pack2(b.x,  b.x);
            bpm[j] = pack2(-b.y, b.y);
        }
        #pragma unroll
        for (int m = 0; m < 4; m++) {
            float2 a = alphaS[(v + 32*m)*129 + x];
            ull au = pack2(a.x, a.y);
            ull as = pack2(a.y, a.x);
            #pragma unroll
            for (int j = 0; j < 5; j++) {
                acc[j][m] = fma2(au, bxx[j], acc[j][m]);
                acc[j][m] = fma2(as, bpm[j], acc[j][m]);
            }
        }
    }
    #pragma unroll
    for (int j = 0; j < 5; j++) {
        float2* dst = g_T2 + ((size_t)bi * CO*M2 + kq0 + u*5 + j) * NY;
        #pragma unroll
        for (int m = 0; m < 4; m++)
            dst[v + 32*m] = unpack2(acc[j][m]);
    }
}

// ---------------- res2[b,k,p,q] = sum_i wr * sum_o A1[p,o]*T2[q,o] ---------
__global__ void k_res2(const float* __restrict__ wr_re, const float* __restrict__ wr_im) {
    int bk = blockIdx.x;
    int b = bk >> 5, k = bk & 31;
    int t = threadIdx.x;
    __shared__ float2 wrS[CI][M1*M2];
    for (int idx = t; idx < CI*M1*M2; idx += 128) {
        int i = idx / (M1*M2), pq = idx % (M1*M2);
        wrS[i][pq] = make_float2(wr_re[(i*CO + k)*M1*M2 + pq], wr_im[(i*CO + k)*M1*M2 + pq]);
    }
    __syncthreads();
    float2 acc[M1*M2];
    #pragma unroll
    for (int j = 0; j < M1*M2; j++) acc[j] = make_float2(0.f, 0.f);
    for (int i = 0; i < CI; i++) {
        float2 a1[M1], t2[M2];
        #pragma unroll
        for (int p = 0; p < M1; p++) a1[p] = g_A1[((i*CO + k)*M1 + p)*NY + t];
        #pragma unroll
        for (int q = 0; q < M2; q++) t2[q] = g_T2[(((size_t)(b*CI + i)*CO + k)*M2 + q)*NY + t];
        #pragma unroll
        for (int p = 0; p < M1; p++)
            #pragma unroll
            for (int q = 0; q < M2; q++) {
                float2 wa = cmul(wrS[i][p*M2 + q], a1[p]);
                acc[p*M2 + q] = cfma(wa, t2[q], acc[p*M2 + q]);
            }
    }
    #pragma unroll
    for (int j = 0; j < M1*M2; j++)
        #pragma unroll
        for (int off = 16; off; off >>= 1) {
            acc[j].x += __shfl_down_sync(0xffffffffu, acc[j].x, off);
            acc[j].y += __shfl_down_sync(0xffffffffu, acc[j].y, off);
        }
    __shared__ float2 red[4][M1*M2];
    int w = t >> 5, lane = t & 31;
    if (lane == 0) {
        #pragma unroll
        for (int j = 0; j < M1*M2; j++) red[w][j] = acc[j];
    }
    __syncthreads();
    if (t < M1*M2) {
        float2 s = red[0][t];
        #pragma unroll
        for (int w2 = 1; w2 < 4; w2++) { s.x += red[w2][t].x; s.y += red[w2][t].y; }
        g_res2[bk*M1*M2 + t] = s;
    }
}

// ---------------- G[b,c,k,q,z] = sum_p res2[b,c,p,q] * E1[c,k,p,z] ---------
__global__ void k_G() {
    int blk = blockIdx.x;
    int b = blk >> 10, c = (blk >> 5) & 31, k = blk & 31;
    int z = threadIdx.x;
    __shared__ float2 r2[M1*M2];
    if (z < M1*M2) r2[z] = g_res2[(b*CO + c)*M1*M2 + z];
    __syncthreads();
    float2 e1[M1];
    #pragma unroll
    for (int p = 0; p < M1; p++) e1[p] = g_E1[((c*CO + k)*M1 + p)*NY + z];
    #pragma unroll
    for (int q = 0; q < M2; q++) {
        float2 acc = make_float2(0.f, 0.f);
        #pragma unroll
        for (int p = 0; p < M1; p++) acc = cfma(r2[p*M2 + q], e1[p], acc);
        g_G[(((size_t)(b*CI + c)*CO + k)*M2 + q)*NY + z] = acc;
    }
}

// ---------------- Hsum for a k-half (16 k values) — stays L2-resident ------
__global__ void k_hsum(const float* __restrict__ wr_re, const float* __restrict__ wr_im,
                       int khalf) {
    int blk = blockIdx.x;                 // i*16 + kh
    int i  = blk >> 4;
    int k  = khalf*16 + (blk & 15);
    int ik = i*CO + k;
    int t  = threadIdx.x;
    __shared__ float2 wrS[M1*M2];
    __shared__ float2 A1S[M1][NY];
    __shared__ float2 U[M2][NY];
    if (t < M1*M2) wrS[t] = make_float2(wr_re[ik*M1*M2 + t], wr_im[ik*M1*M2 + t]);
    #pragma unroll
    for (int p = 0; p < M1; p++) A1S[p][t] = g_A1[(ik*M1 + p)*NY + t];
    float2 a2[M2];
    #pragma unroll
    for (int q = 0; q < M2; q++) a2[q] = g_A2[(ik*M2 + q)*NX + t];
    __syncthreads();
    #pragma unroll
    for (int q = 0; q < M2; q++) {
        float2 acc = make_float2(0.f, 0.f);
        #pragma unroll
        for (int p = 0; p < M1; p++) acc = cfma(wrS[p*M2 + q], A1S[p][t], acc);
        U[q][t] = acc;
    }
    __syncthreads();
    float2* H = g_H + (size_t)ik * NY * NX;
    for (int o = 0; o < NY; o++) {
        float2 acc = make_float2(0.f, 0.f);
        #pragma unroll
        for (int q = 0; q < M2; q++) acc = cfma(U[q][o], a2[q], acc);
        H[o*NX + t] = acc;
    }
}

// ---------------- res1 (k-half) fused with inverse row FFT -----------------
// block: (k-tile of 4 within half, o). Computes res1 rows for 4k x 8b, then
// does 32 inverse 128-pt FFTs in smem and writes g_tmp directly.
__global__ void __launch_bounds__(128) k_res1f(int khalf) {
    __shared__ float2 rows[32][129];
    __shared__ float2 tws[64];
    int o  = blockIdx.x & 127;
    int k0 = khalf*16 + (blockIdx.x >> 7) * 4;
    int x  = threadIdx.x;
    make_tws(tws, x);
    ull acc[4][B];
    #pragma unroll
    for (int kk = 0; kk < 4; kk++)
        #pragma unroll
        for (int b = 0; b < B; b++) acc[kk][b] = pack2(0.f, 0.f);
    for (int i = 0; i < CI; i++) {
        ull hxx[4], hpm[4];
        #pragma unroll
        for (int kk = 0; kk < 4; kk++) {
            float2 h = g_H[((size_t)(i*CO + k0 + kk) * NY + o) * NX + x];
            hxx[kk] = pack2(h.x,  h.x);
            hpm[kk] = pack2(-h.y, h.y);
        }
        #pragma unroll
        for (int b = 0; b < B; b++) {
            float2 a = g_alpha[((size_t)(b*CI + i) * NY + o) * NX + x];
            ull au = pack2(a.x, a.y);
            ull as = pack2(a.y, a.x);
            #pragma unroll
            for (int kk = 0; kk < 4; kk++) {
                acc[kk][b] = fma2(au, hxx[kk], acc[kk][b]);
                acc[kk][b] = fma2(as, hpm[kk], acc[kk][b]);
            }
        }
    }
    // bit-reversed scatter into smem rows
    int xr = __brev(x) >> 25;
    #pragma unroll
    for (int kk = 0; kk < 4; kk++)
        #pragma unroll
        for (int b = 0; b < B; b++)
            rows[kk*8 + b][xr] = unpack2(acc[kk][b]);
    __syncthreads();
    // 32 inverse FFTs: each stage, thread handles 16 butterflies
    #pragma unroll
    for (int stage = 1; stage <= 7; stage++) {
        int half = 1 << (stage - 1);
        #pragma unroll
        for (int m = 0; m < 16; m++) {
            int l = x + 128*m;
            int r = l >> 6, j = l & 63;
            int p = j & (half - 1);
            int i0 = ((j >> (stage - 1)) << stage) + p;
            int i1 = i0 + half;
            float2 w = tws[p << (7 - stage)];
            float2 u = rows[r][i0], v0 = rows[r][i1];
            float2 v = make_float2(v0.x*w.x + v0.y*w.y, -v0.x*w.y + v0.y*w.x);
            rows[r][i0] = make_float2(u.x + v.x, u.y + v.y);
            rows[r][i1] = make_float2(u.x - v.x, u.y - v.y);
        }
        __syncthreads();
    }
    #pragma unroll
    for (int kk = 0; kk < 4; kk++)
        #pragma unroll
        for (int b = 0; b < B; b++)
            g_tmp[(((size_t)(b*CO + k0 + kk)) * NY + o) * NX + x] = rows[kk*8 + b][x];
}

// inverse columns + real part + scale: g_tmp -> out
__global__ void k_ifft_cols_r(float* __restrict__ out) {
    __shared__ float2 tile[NY][17];
    __shared__ float2 tws[64];
    int t = threadIdx.x;
    make_tws(tws, t);
    int blk = blockIdx.x;
    int xt = blk & 7, img = blk >> 3;
    int x0 = xt * 16;
    int tg = t >> 4, tx = t & 15;
    const float2* base = g_tmp + (size_t)img * NY * NX + x0;
    #pragma unroll
    for (int c = 0; c < 16; c++) {
        int y = c * 8 + tg;
        tile[__brev(y) >> 25][tx] = base[(size_t)y * NX + tx];
    }
    fft_col<1>(tile, tg, tx, tws);
    __syncthreads();
    const float INV = 1.0f / (float)(NY * NX);
    float* ob = out + (size_t)img * NY * NX + x0;
    #pragma unroll
    for (int c = 0; c < 16; c++) {
        int y = c * 8 + tg;
        ob[(size_t)y * NX + tx] = tile[y][tx].x * INV;
    }
}

// ---------------- x2: out += Re( G[z,cq] * E2[cq,x] ) / (NY*NX) ------------
__global__ void __launch_bounds__(256, 2) k_x2(float* __restrict__ out) {
    __shared__ float2 Gs[16][65];
    __shared__ float2 Es[16][129];
    int blk = blockIdx.x;
    int zh  = blk & 1;
    int bk  = blk >> 1;
    int b = bk >> 5, k = bk & 31;
    int z0 = zh * 64;
    int t = threadIdx.x;
    int u = t >> 5, v = t & 31;
    ull acc[8][4];
    #pragma unroll
    for (int j = 0; j < 8; j++)
        #pragma unroll
        for (int m = 0; m < 4; m++) acc[j][m] = pack2(0.f, 0.f);
    for (int k0 = 0; k0 < CI*M2; k0 += 16) {
        __syncthreads();
        for (int l = t; l < 16*64; l += 256) {
            int r = l >> 6, zz = l & 63;
            int cq = k0 + r; int c = cq / M2, q = cq % M2;
            Gs[r][zz] = g_G[(((size_t)(b*CI + c)*CO + k)*M2 + q)*NY + z0 + zz];
        }
        for (int l = t; l < 16*128; l += 256) {
            int r = l >> 7, xx = l & 127;
            int cq = k0 + r; int c = cq / M2, q = cq % M2;
            Es[r][xx] = g_E2[((size_t)(c*CO + k)*M2 + q)*NX + xx];
        }
        __syncthreads();
        #pragma unroll
        for (int kk = 0; kk < 16; kk++) {
            ull gpm[8];
            #pragma unroll
            for (int j = 0; j < 8; j++) {
                float2 g = Gs[kk][u*8 + j];
                gpm[j] = pack2(g.x, -g.y);
            }
            #pragma unroll
            for (int m = 0; m < 4; m++) {
                float2 e = Es[kk][v + 32*m];
                ull eu = pack2(e.x, e.y);
                #pragma unroll
                for (int j = 0; j < 8; j++)
                    acc[j][m] = fma2(eu, gpm[j], acc[j][m]);
            }
        }
    }
    const float INV = 1.0f / (float)(NY * NX);
    float* ob = out + (size_t)(b*CO + k) * NY * NX;
    #pragma unroll
    for (int j = 0; j < 8; j++) {
        int z = z0 + u*8 + j;
        #pragma unroll
        for (int m = 0; m < 4; m++) {
            float2 r = unpack2(acc[j][m]);
            ob[(size_t)z * NX + v + 32*m] += (r.x + r.y) * INV;
        }
    }
}

// ---------------------------------------------------------------------------
extern "C" void kernel_launch(void* const* d_in, const int* in_sizes, int n_in,
                              void* d_out, int out_size) {
    const float* x      = (const float*)d_in[0];
    const float* wp1_re = (const float*)d_in[1];
    const float* wp1_im = (const float*)d_in[2];
    const float* wp2_re = (const float*)d_in[3];
    const float* wp2_im = (const float*)d_in[4];
    const float* wr_re  = (const float*)d_in[5];
    const float* wr_im  = (const float*)d_in[6];
    const float* ty     = (const float*)d_in[7];
    const float* tx     = (const float*)d_in[8];
    float* out = (float*)d_out;

    cudaFuncSetAttribute(k_T2, cudaFuncAttributeMaxDynamicSharedMemorySize, (int)T2_SMEM);

    k_fac         <<<CI*CO*(M1+M2), 128>>>(wp1_re, wp1_im, wp2_re, wp2_im, ty, tx);  // 0
    k_fft_rows_f  <<<B*CI*NY/2, 128>>>(x);                                           // 1
    k_fft_cols_f  <<<B*CI*8, 128>>>();                                               // 2
    k_T2          <<<B*CI*4, 256, T2_SMEM>>>();                                      // 3 (profiled)
    k_res2        <<<B*CO, 128>>>(wr_re, wr_im);                                     // 4
    k_G           <<<B*CI*CO, 128>>>();                                              // 5
    // H path, interleaved by k-halves so H stays L2-resident
    k_hsum        <<<CI*16, 128>>>(wr_re, wr_im, 0);                                 // 6
    k_res1f       <<<4*NY, 128>>>(0);                                                // 7
    k_hsum        <<<CI*16, 128>>>(wr_re, wr_im, 1);                                 // 8
    k_res1f       <<<4*NY, 128>>>(1);                                                // 9
    k_ifft_cols_r <<<B*CO*8, 128>>>(out);                                            // 10
    k_x2          <<<B*CO*2, 256>>>(out);                                            // 11
}

// round 6
// speedup vs baseline: 1.1169x; 1.1169x over previous
#include <cuda_runtime.h>

#define B   8
#define CI  32
#define CO  32
#define NY  128
#define NX  128
#define M1  4
#define M2  5

#define TWO_PI_F 6.283185307179586476925f

typedef unsigned long long ull;

__device__ __forceinline__ float2 cmul(float2 a, float2 b) {
    return make_float2(a.x*b.x - a.y*b.y, a.x*b.y + a.y*b.x);
}
__device__ __forceinline__ float2 cfma(float2 a, float2 b, float2 c) {
    c.x = fmaf(a.x, b.x, fmaf(-a.y, b.y, c.x));
    c.y = fmaf(a.x, b.y, fmaf( a.y, b.x, c.y));
    return c;
}
__device__ __forceinline__ ull pack2(float lo, float hi) {
    ull r; asm("mov.b64 %0, {%1, %2};" : "=l"(r) : "f"(lo), "f"(hi)); return r;
}
__device__ __forceinline__ float2 unpack2(ull v) {
    float2 f; asm("mov.b64 {%0, %1}, %2;" : "=f"(f.x), "=f"(f.y) : "l"(v)); return f;
}
__device__ __forceinline__ ull fma2(ull a, ull b, ull c) {
    ull d; asm("fma.rn.f32x2 %0, %1, %2, %3;" : "=l"(d) : "l"(a), "l"(b), "l"(c)); return d;
}

// ---------------- scratch ---------------------------------------------------
__device__ float2 g_tmp  [B*CI*NY*NX];
__device__ float2 g_alpha[B*CI*NY*NX];
__device__ float2 g_A1   [CI*CO*M1*NY];
__device__ float2 g_A2   [CI*CO*M2*NX];
__device__ float2 g_E1   [CI*CO*M1*NY];
__device__ float2 g_E2   [CI*CO*M2*NX];
__device__ float2 g_H    [CI*CO*NY*NX];
__device__ float2 g_T2   [B*CI*CO*M2*NY];
__device__ float2 g_res2 [B*CO*M1*M2];
__device__ float2 g_G    [B*CI*CO*M2*NY];

__device__ __forceinline__ void make_tws(float2* tws, int t) {
    if (t < 64) {
        float sn, cs;
        sincospif(-(float)t / 64.f, &sn, &cs);
        tws[t] = make_float2(cs, sn);
    }
}

// ---------------- merged pole factors (launch 0) ----------------------------
__global__ void k_fac(const float* __restrict__ wp1_re, const float* __restrict__ wp1_im,
                      const float* __restrict__ wp2_re, const float* __restrict__ wp2_im,
                      const float* __restrict__ ty, const float* __restrict__ tx) {
    int blk = blockIdx.x;
    int o   = threadIdx.x;
    if (blk < CI*CO*M1) {
        int ikp = blk;
        float wr = wp1_re[ikp], wi = wp1_im[ikp];
        float d = ty[1] - ty[0];
        float invnd = 1.0f / ((float)NY * d);
        float k = (o < NY/2) ? (float)o : (float)(o - NY);
        float lam = TWO_PI_F * k * invnd;
        float a = -wr, b = lam - wi;
        float inv = 1.0f / (a*a + b*b);
        g_A1[ikp*NY + o] = make_float2(a*inv, -b*inv);
        float t = ty[o];
        float e = expf(wr * t);
        float sn, cs; sincosf(wi * t, &sn, &cs);
        g_E1[ikp*NY + o] = make_float2(e*cs, e*sn);
    } else {
        int ikq = blk - CI*CO*M1;
        float wr = wp2_re[ikq], wi = wp2_im[ikq];
        float d = tx[1] - tx[0];
        float invnd = 1.0f / ((float)NX * d);
        float k = (o < NX/2) ? (float)o : (float)(o - NX);
        float lam = TWO_PI_F * k * invnd;
        float a = -wr, b = lam - wi;
        float inv = 1.0f / (a*a + b*b);
        g_A2[ikq*NX + o] = make_float2(a*inv, -b*inv);
        float t = tx[o];
        float e = expf(wr * t);
        float sn, cs; sincosf(wi * t, &sn, &cs);
        g_E2[ikq*NX + o] = make_float2(e*cs, e*sn);
    }
}

// ---------------- 128-pt radix-2 DIT ----------------------------------------
template<int INV>
__device__ __forceinline__ void fft64th(float2* s, int tt, const float2* tws) {
    #pragma unroll
    for (int stage = 1; stage <= 7; stage++) {
        __syncthreads();
        int half = 1 << (stage - 1);
        int p  = tt & (half - 1);
        int i0 = ((tt >> (stage - 1)) << stage) + p;
        int i1 = i0 + half;
        float2 w = tws[p << (7 - stage)];
        float wy = INV ? -w.y : w.y;
        float2 u = s[i0], v0 = s[i1];
        float2 v = make_float2(v0.x*w.x - v0.y*wy, v0.x*wy + v0.y*w.x);
        s[i0] = make_float2(u.x + v.x, u.y + v.y);
        s[i1] = make_float2(u.x - v.x, u.y - v.y);
    }
}

// forward FFT of real rows (launch 1)
__global__ void k_fft_rows_f(const float* __restrict__ x) {
    __shared__ float2 s[2][NX];
    __shared__ float2 tws[64];
    int t = threadIdx.x, r = t >> 6, tt = t & 63;
    make_tws(tws, t);
    size_t row = (size_t)blockIdx.x * 2 + r;
    const float* xr = x + row * NX;
    s[r][tt]      = make_float2(xr[__brev(tt)      >> 25], 0.f);
    s[r][tt + 64] = make_float2(xr[__brev(tt + 64) >> 25], 0.f);
    fft64th<0>(s[r], tt, tws);
    float2* o = g_tmp + row * NX;
    o[tt] = s[r][tt]; o[tt + 64] = s[r][tt + 64];
}

template<int INV>
__device__ __forceinline__ void fft_col(float2 (*tile)[17], int tg, int tx, const float2* tws) {
    #pragma unroll
    for (int stage = 1; stage <= 7; stage++) {
        __syncthreads();
        int half = 1 << (stage - 1);
        #pragma unroll
        for (int m = 0; m < 8; m++) {
            int j  = tg + 8 * m;
            int p  = j & (half - 1);
            int i0 = ((j >> (stage - 1)) << stage) + p;
            int i1 = i0 + half;
            float2 w = tws[p << (7 - stage)];
            float wy = INV ? -w.y : w.y;
            float2 u = tile[i0][tx], v0 = tile[i1][tx];
            float2 v = make_float2(v0.x*w.x - v0.y*wy, v0.x*wy + v0.y*w.x);
            tile[i0][tx] = make_float2(u.x + v.x, u.y + v.y);
            tile[i1][tx] = make_float2(u.x - v.x, u.y - v.y);
        }
    }
}

// forward columns (launch 2): g_tmp -> g_alpha
__global__ void k_fft_cols_f() {
    __shared__ float2 tile[NY][17];
    __shared__ float2 tws[64];
    int t = threadIdx.x;
    make_tws(tws, t);
    int blk = blockIdx.x;
    int xt = blk & 7, img = blk >> 3;
    int x0 = xt * 16;
    int tg = t >> 4, tx = t & 15;
    const float2* base = g_tmp + (size_t)img * NY * NX + x0;
    #pragma unroll
    for (int c = 0; c < 16; c++) {
        int y = c * 8 + tg;
        tile[__brev(y) >> 25][tx] = base[(size_t)y * NX + tx];
    }
    fft_col<0>(tile, tg, tx, tws);
    __syncthreads();
    float2* ob = g_alpha + (size_t)img * NY * NX + x0;
    #pragma unroll
    for (int c = 0; c < 16; c++) {
        int y = c * 8 + tg;
        ob[(size_t)y * NX + tx] = tile[y][tx];
    }
}

// ---------------- T2: 2 blocks/SM, o-tile 64, kq chunks of 40 (launch 3) ----
#define T2_OT 64
#define T2_KC 40
#define T2_SMEM ((T2_OT*129 + T2_KC*129) * sizeof(float2))
extern __shared__ float2 t2sm[];
__global__ void __launch_bounds__(256, 2) k_T2() {
    float2* alphaS = t2sm;                   // [64 o][129 x]
    float2* a2S    = t2sm + T2_OT*129;       // [40 kq][129 x]
    int blk = blockIdx.x;
    int oh = blk & 1;
    int bi = blk >> 1;
    int i  = bi & 31;
    int o0 = oh * T2_OT;
    int t  = threadIdx.x;
    const float2* A = g_alpha + (size_t)bi * NY * NX + (size_t)o0 * NX;
    #pragma unroll 4
    for (int l = t; l < T2_OT*128; l += 256) {
        int o = l >> 7, x = l & 127;
        alphaS[o*129 + x] = A[(size_t)o * NX + x];
    }
    int u = t >> 5, v = t & 31;
    #pragma unroll 1
    for (int c = 0; c < 4; c++) {
        int kq0 = c * T2_KC;
        __syncthreads();
        for (int l = t; l < T2_KC*128; l += 256) {
            int r = l >> 7, x = l & 127;
            a2S[r*129 + x] = g_A2[(size_t)(i*CO*M2 + kq0 + r) * NX + x];
        }
        __syncthreads();
        ull acc[5][2];
        #pragma unroll
        for (int j = 0; j < 5; j++)
            #pragma unroll
            for (int m = 0; m < 2; m++) acc[j][m] = pack2(0.f, 0.f);
        #pragma unroll 2
        for (int x = 0; x < 128; x++) {
            ull bxx[5], bpm[5];
            #pragma unroll
            for (int j = 0; j < 5; j++) {
                float2 b = a2S[(u*5 + j)*129 + x];
                bxx[j] = pack2(b.x,  b.x);
                bpm[j] = pack2(-b.y, b.y);
            }
            #pragma unroll
            for (int m = 0; m < 2; m++) {
                float2 a = alphaS[(v + 32*m)*129 + x];
                ull au = pack2(a.x, a.y);
                ull as = pack2(a.y, a.x);
                #pragma unroll
                for (int j = 0; j < 5; j++) {
                    acc[j][m] = fma2(au, bxx[j], acc[j][m]);
                    acc[j][m] = fma2(as, bpm[j], acc[j][m]);
                }
            }
        }
        #pragma unroll
        for (int j = 0; j < 5; j++) {
            float2* dst = g_T2 + ((size_t)bi * CO*M2 + kq0 + u*5 + j) * NY + o0;
            #pragma unroll
            for (int m = 0; m < 2; m++)
                dst[v + 32*m] = unpack2(acc[j][m]);
        }
    }
}

// ---------------- res2[b,k,p,q] = sum_i wr * sum_o A1[p,o]*T2[q,o] ---------
__global__ void k_res2(const float* __restrict__ wr_re, const float* __restrict__ wr_im) {
    int bk = blockIdx.x;
    int b = bk >> 5, k = bk & 31;
    int t = threadIdx.x;
    __shared__ float2 wrS[CI][M1*M2];
    for (int idx = t; idx < CI*M1*M2; idx += 128) {
        int i = idx / (M1*M2), pq = idx % (M1*M2);
        wrS[i][pq] = make_float2(wr_re[(i*CO + k)*M1*M2 + pq], wr_im[(i*CO + k)*M1*M2 + pq]);
    }
    __syncthreads();
    float2 acc[M1*M2];
    #pragma unroll
    for (int j = 0; j < M1*M2; j++) acc[j] = make_float2(0.f, 0.f);
    for (int i = 0; i < CI; i++) {
        float2 a1[M1], t2[M2];
        #pragma unroll
        for (int p = 0; p < M1; p++) a1[p] = g_A1[((i*CO + k)*M1 + p)*NY + t];
        #pragma unroll
        for (int q = 0; q < M2; q++) t2[q] = g_T2[(((size_t)(b*CI + i)*CO + k)*M2 + q)*NY + t];
        #pragma unroll
        for (int p = 0; p < M1; p++)
            #pragma unroll
            for (int q = 0; q < M2; q++) {
                float2 wa = cmul(wrS[i][p*M2 + q], a1[p]);
                acc[p*M2 + q] = cfma(wa, t2[q], acc[p*M2 + q]);
            }
    }
    #pragma unroll
    for (int j = 0; j < M1*M2; j++)
        #pragma unroll
        for (int off = 16; off; off >>= 1) {
            acc[j].x += __shfl_down_sync(0xffffffffu, acc[j].x, off);
            acc[j].y += __shfl_down_sync(0xffffffffu, acc[j].y, off);
        }
    __shared__ float2 red[4][M1*M2];
    int w = t >> 5, lane = t & 31;
    if (lane == 0) {
        #pragma unroll
        for (int j = 0; j < M1*M2; j++) red[w][j] = acc[j];
    }
    __syncthreads();
    if (t < M1*M2) {
        float2 s = red[0][t];
        #pragma unroll
        for (int w2 = 1; w2 < 4; w2++) { s.x += red[w2][t].x; s.y += red[w2][t].y; }
        g_res2[bk*M1*M2 + t] = s;
    }
}

// ---------------- G[b,c,k,q,z] = sum_p res2[b,c,p,q] * E1[c,k,p,z] ---------
__global__ void k_G() {
    int blk = blockIdx.x;
    int b = blk >> 10, c = (blk >> 5) & 31, k = blk & 31;
    int z = threadIdx.x;
    __shared__ float2 r2[M1*M2];
    if (z < M1*M2) r2[z] = g_res2[(b*CO + c)*M1*M2 + z];
    __syncthreads();
    float2 e1[M1];
    #pragma unroll
    for (int p = 0; p < M1; p++) e1[p] = g_E1[((c*CO + k)*M1 + p)*NY + z];
    #pragma unroll
    for (int q = 0; q < M2; q++) {
        float2 acc = make_float2(0.f, 0.f);
        #pragma unroll
        for (int p = 0; p < M1; p++) acc = cfma(r2[p*M2 + q], e1[p], acc);
        g_G[(((size_t)(b*CI + c)*CO + k)*M2 + q)*NY + z] = acc;
    }
}

// ---------------- Hsum full (streaming stores) ------------------------------
__global__ void k_hsum(const float* __restrict__ wr_re, const float* __restrict__ wr_im) {
    int ik = blockIdx.x;
    int t  = threadIdx.x;
    __shared__ float2 wrS[M1*M2];
    __shared__ float2 A1S[M1][NY];
    __shared__ float2 U[M2][NY];
    if (t < M1*M2) wrS[t] = make_float2(wr_re[ik*M1*M2 + t], wr_im[ik*M1*M2 + t]);
    #pragma unroll
    for (int p = 0; p < M1; p++) A1S[p][t] = g_A1[(ik*M1 + p)*NY + t];
    float2 a2[M2];
    #pragma unroll
    for (int q = 0; q < M2; q++) a2[q] = g_A2[(ik*M2 + q)*NX + t];
    __syncthreads();
    #pragma unroll
    for (int q = 0; q < M2; q++) {
        float2 acc = make_float2(0.f, 0.f);
        #pragma unroll
        for (int p = 0; p < M1; p++) acc = cfma(wrS[p*M2 + q], A1S[p][t], acc);
        U[q][t] = acc;
    }
    __syncthreads();
    float2* H = g_H + (size_t)ik * NY * NX;
    for (int o = 0; o < NY; o++) {
        float2 acc = make_float2(0.f, 0.f);
        #pragma unroll
        for (int q = 0; q < M2; q++) acc = cfma(U[q][o], a2[q], acc);
        __stcs(&H[o*NX + t], acc);
    }
}

// ---------------- res1 fused with inverse row FFT (full k range) ------------
__global__ void __launch_bounds__(128) k_res1f() {
    __shared__ float2 rows[32][129];
    __shared__ float2 tws[64];
    int o  = blockIdx.x & 127;
    int k0 = (blockIdx.x >> 7) * 4;
    int x  = threadIdx.x;
    make_tws(tws, x);
    ull acc[4][B];
    #pragma unroll
    for (int kk = 0; kk < 4; kk++)
        #pragma unroll
        for (int b = 0; b < B; b++) acc[kk][b] = pack2(0.f, 0.f);
    for (int i = 0; i < CI; i++) {
        ull hxx[4], hpm[4];
        #pragma unroll
        for (int kk = 0; kk < 4; kk++) {
            float2 h = __ldcs(&g_H[((size_t)(i*CO + k0 + kk) * NY + o) * NX + x]);
            hxx[kk] = pack2(h.x,  h.x);
            hpm[kk] = pack2(-h.y, h.y);
        }
        #pragma unroll
        for (int b = 0; b < B; b++) {
            float2 a = g_alpha[((size_t)(b*CI + i) * NY + o) * NX + x];
            ull au = pack2(a.x, a.y);
            ull as = pack2(a.y, a.x);
            #pragma unroll
            for (int kk = 0; kk < 4; kk++) {
                acc[kk][b] = fma2(au, hxx[kk], acc[kk][b]);
                acc[kk][b] = fma2(as, hpm[kk], acc[kk][b]);
            }
        }
    }
    int xr = __brev(x) >> 25;
    #pragma unroll
    for (int kk = 0; kk < 4; kk++)
        #pragma unroll
        for (int b = 0; b < B; b++)
            rows[kk*8 + b][xr] = unpack2(acc[kk][b]);
    __syncthreads();
    #pragma unroll
    for (int stage = 1; stage <= 7; stage++) {
        int half = 1 << (stage - 1);
        #pragma unroll
        for (int m = 0; m < 16; m++) {
            int l = x + 128*m;
            int r = l >> 6, j = l & 63;
            int p = j & (half - 1);
            int i0 = ((j >> (stage - 1)) << stage) + p;
            int i1 = i0 + half;
            float2 w = tws[p << (7 - stage)];
            float2 u = rows[r][i0], v0 = rows[r][i1];
            float2 v = make_float2(v0.x*w.x + v0.y*w.y, -v0.x*w.y + v0.y*w.x);
            rows[r][i0] = make_float2(u.x + v.x, u.y + v.y);
            rows[r][i1] = make_float2(u.x - v.x, u.y - v.y);
        }
        __syncthreads();
    }
    #pragma unroll
    for (int kk = 0; kk < 4; kk++)
        #pragma unroll
        for (int b = 0; b < B; b++)
            g_tmp[(((size_t)(b*CO + k0 + kk)) * NY + o) * NX + x] = rows[kk*8 + b][x];
}

// inverse columns + real part + scale: g_tmp -> out
__global__ void k_ifft_cols_r(float* __restrict__ out) {
    __shared__ float2 tile[NY][17];
    __shared__ float2 tws[64];
    int t = threadIdx.x;
    make_tws(tws, t);
    int blk = blockIdx.x;
    int xt = blk & 7, img = blk >> 3;
    int x0 = xt * 16;
    int tg = t >> 4, tx = t & 15;
    const float2* base = g_tmp + (size_t)img * NY * NX + x0;
    #pragma unroll
    for (int c = 0; c < 16; c++) {
        int y = c * 8 + tg;
        tile[__brev(y) >> 25][tx] = base[(size_t)y * NX + tx];
    }
    fft_col<1>(tile, tg, tx, tws);
    __syncthreads();
    const float INV = 1.0f / (float)(NY * NX);
    float* ob = out + (size_t)img * NY * NX + x0;
    #pragma unroll
    for (int c = 0; c < 16; c++) {
        int y = c * 8 + tg;
        ob[(size_t)y * NX + tx] = tile[y][tx].x * INV;
    }
}

// ---------------- x2: out += Re( G[z,cq] * E2[cq,x] ) / (NY*NX) ------------
__global__ void __launch_bounds__(256, 2) k_x2(float* __restrict__ out) {
    __shared__ float2 Gs[16][65];
    __shared__ float2 Es[16][129];
    int blk = blockIdx.x;
    int zh  = blk & 1;
    int bk  = blk >> 1;
    int b = bk >> 5, k = bk & 31;
    int z0 = zh * 64;
    int t = threadIdx.x;
    int u = t >> 5, v = t & 31;
    ull acc[8][4];
    #pragma unroll
    for (int j = 0; j < 8; j++)
        #pragma unroll
        for (int m = 0; m < 4; m++) acc[j][m] = pack2(0.f, 0.f);
    for (int k0 = 0; k0 < CI*M2; k0 += 16) {
        __syncthreads();
        for (int l = t; l < 16*64; l += 256) {
            int r = l >> 6, zz = l & 63;
            int cq = k0 + r; int c = cq / M2, q = cq % M2;
            Gs[r][zz] = g_G[(((size_t)(b*CI + c)*CO + k)*M2 + q)*NY + z0 + zz];
        }
        for (int l = t; l < 16*128; l += 256) {
            int r = l >> 7, xx = l & 127;
            int cq = k0 + r; int c = cq / M2, q = cq % M2;
            Es[r][xx] = g_E2[((size_t)(c*CO + k)*M2 + q)*NX + xx];
        }
        __syncthreads();
        #pragma unroll
        for (int kk = 0; kk < 16; kk++) {
            ull gpm[8];
            #pragma unroll
            for (int j = 0; j < 8; j++) {
                float2 g = Gs[kk][u*8 + j];
                gpm[j] = pack2(g.x, -g.y);
            }
            #pragma unroll
            for (int m = 0; m < 4; m++) {
                float2 e = Es[kk][v + 32*m];
                ull eu = pack2(e.x, e.y);
                #pragma unroll
                for (int j = 0; j < 8; j++)
                    acc[j][m] = fma2(eu, gpm[j], acc[j][m]);
            }
        }
    }
    const float INV = 1.0f / (float)(NY * NX);
    float* ob = out + (size_t)(b*CO + k) * NY * NX;
    #pragma unroll
    for (int j = 0; j < 8; j++) {
        int z = z0 + u*8 + j;
        #pragma unroll
        for (int m = 0; m < 4; m++) {
            float2 r = unpack2(acc[j][m]);
            ob[(size_t)z * NX + v + 32*m] += (r.x + r.y) * INV;
        }
    }
}

// ---------------------------------------------------------------------------
extern "C" void kernel_launch(void* const* d_in, const int* in_sizes, int n_in,
                              void* d_out, int out_size) {
    const float* x      = (const float*)d_in[0];
    const float* wp1_re = (const float*)d_in[1];
    const float* wp1_im = (const float*)d_in[2];
    const float* wp2_re = (const float*)d_in[3];
    const float* wp2_im = (const float*)d_in[4];
    const float* wr_re  = (const float*)d_in[5];
    const float* wr_im  = (const float*)d_in[6];
    const float* ty     = (const float*)d_in[7];
    const float* tx     = (const float*)d_in[8];
    float* out = (float*)d_out;

    cudaFuncSetAttribute(k_T2, cudaFuncAttributeMaxDynamicSharedMemorySize, (int)T2_SMEM);

    k_fac         <<<CI*CO*(M1+M2), 128>>>(wp1_re, wp1_im, wp2_re, wp2_im, ty, tx);  // 0
    k_fft_rows_f  <<<B*CI*NY/2, 128>>>(x);                                           // 1
    k_fft_cols_f  <<<B*CI*8, 128>>>();                                               // 2
    k_T2          <<<B*CI*2, 256, T2_SMEM>>>();                                      // 3 (profiled)
    k_res2        <<<B*CO, 128>>>(wr_re, wr_im);                                     // 4
    k_G           <<<B*CI*CO, 128>>>();                                              // 5
    k_hsum        <<<CI*CO, 128>>>(wr_re, wr_im);                                    // 6
    k_res1f       <<<8*NY, 128>>>();                                                 // 7
    k_ifft_cols_r <<<B*CO*8, 128>>>(out);                                            // 8
    k_x2          <<<B*CO*2, 256>>>(out);                                            // 9
}

// round 7
// speedup vs baseline: 1.1361x; 1.0172x over previous
#include <cuda_runtime.h>

#define B   8
#define CI  32
#define CO  32
#define NY  128
#define NX  128
#define M1  4
#define M2  5

#define TWO_PI_F 6.283185307179586476925f

typedef unsigned long long ull;

__device__ __forceinline__ float2 cmul(float2 a, float2 b) {
    return make_float2(a.x*b.x - a.y*b.y, a.x*b.y + a.y*b.x);
}
__device__ __forceinline__ float2 cfma(float2 a, float2 b, float2 c) {
    c.x = fmaf(a.x, b.x, fmaf(-a.y, b.y, c.x));
    c.y = fmaf(a.x, b.y, fmaf( a.y, b.x, c.y));
    return c;
}
__device__ __forceinline__ ull pack2(float lo, float hi) {
    ull r; asm("mov.b64 %0, {%1, %2};" : "=l"(r) : "f"(lo), "f"(hi)); return r;
}
__device__ __forceinline__ float2 unpack2(ull v) {
    float2 f; asm("mov.b64 {%0, %1}, %2;" : "=f"(f.x), "=f"(f.y) : "l"(v)); return f;
}
__device__ __forceinline__ ull fma2(ull a, ull b, ull c) {
    ull d; asm("fma.rn.f32x2 %0, %1, %2, %3;" : "=l"(d) : "l"(a), "l"(b), "l"(c)); return d;
}
__device__ __forceinline__ ull swap2(ull a) {
    float2 f = unpack2(a);
    return pack2(f.y, f.x);
}

// ---------------- scratch ---------------------------------------------------
__device__ float2 g_tmp  [B*CI*NY*NX];
__device__ float2 g_alpha[B*CI*NY*NX];
__device__ float2 g_A1   [CI*CO*M1*NY];
__device__ float2 g_A2   [CI*CO*M2*NX];
__device__ float2 g_E1   [CI*CO*M1*NY];
__device__ float2 g_E2   [CI*CO*M2*NX];
__device__ float2 g_H    [CI*CO*NY*NX];
__device__ float2 g_T2   [B*CI*CO*M2*NY];
__device__ float2 g_res2 [B*CO*M1*M2];
__device__ float2 g_G    [B*CI*CO*M2*NY];

__device__ __forceinline__ void make_tws(float2* tws, int t) {
    if (t < 64) {
        float sn, cs;
        sincospif(-(float)t / 64.f, &sn, &cs);
        tws[t] = make_float2(cs, sn);
    }
}

// ---------------- merged pole factors (launch 0) ----------------------------
__global__ void k_fac(const float* __restrict__ wp1_re, const float* __restrict__ wp1_im,
                      const float* __restrict__ wp2_re, const float* __restrict__ wp2_im,
                      const float* __restrict__ ty, const float* __restrict__ tx) {
    int blk = blockIdx.x;
    int o   = threadIdx.x;
    if (blk < CI*CO*M1) {
        int ikp = blk;
        float wr = wp1_re[ikp], wi = wp1_im[ikp];
        float d = ty[1] - ty[0];
        float invnd = 1.0f / ((float)NY * d);
        float k = (o < NY/2) ? (float)o : (float)(o - NY);
        float lam = TWO_PI_F * k * invnd;
        float a = -wr, b = lam - wi;
        float inv = 1.0f / (a*a + b*b);
        g_A1[ikp*NY + o] = make_float2(a*inv, -b*inv);
        float t = ty[o];
        float e = expf(wr * t);
        float sn, cs; sincosf(wi * t, &sn, &cs);
        g_E1[ikp*NY + o] = make_float2(e*cs, e*sn);
    } else {
        int ikq = blk - CI*CO*M1;
        float wr = wp2_re[ikq], wi = wp2_im[ikq];
        float d = tx[1] - tx[0];
        float invnd = 1.0f / ((float)NX * d);
        float k = (o < NX/2) ? (float)o : (float)(o - NX);
        float lam = TWO_PI_F * k * invnd;
        float a = -wr, b = lam - wi;
        float inv = 1.0f / (a*a + b*b);
        g_A2[ikq*NX + o] = make_float2(a*inv, -b*inv);
        float t = tx[o];
        float e = expf(wr * t);
        float sn, cs; sincosf(wi * t, &sn, &cs);
        g_E2[ikq*NX + o] = make_float2(e*cs, e*sn);
    }
}

// ---------------- 128-pt radix-2 DIT ----------------------------------------
template<int INV>
__device__ __forceinline__ void fft64th(float2* s, int tt, const float2* tws) {
    #pragma unroll
    for (int stage = 1; stage <= 7; stage++) {
        __syncthreads();
        int half = 1 << (stage - 1);
        int p  = tt & (half - 1);
        int i0 = ((tt >> (stage - 1)) << stage) + p;
        int i1 = i0 + half;
        float2 w = tws[p << (7 - stage)];
        float wy = INV ? -w.y : w.y;
        float2 u = s[i0], v0 = s[i1];
        float2 v = make_float2(v0.x*w.x - v0.y*wy, v0.x*wy + v0.y*w.x);
        s[i0] = make_float2(u.x + v.x, u.y + v.y);
        s[i1] = make_float2(u.x - v.x, u.y - v.y);
    }
}

// forward FFT of real rows (launch 1)
__global__ void k_fft_rows_f(const float* __restrict__ x) {
    __shared__ float2 s[2][NX];
    __shared__ float2 tws[64];
    int t = threadIdx.x, r = t >> 6, tt = t & 63;
    make_tws(tws, t);
    size_t row = (size_t)blockIdx.x * 2 + r;
    const float* xr = x + row * NX;
    s[r][tt]      = make_float2(xr[__brev(tt)      >> 25], 0.f);
    s[r][tt + 64] = make_float2(xr[__brev(tt + 64) >> 25], 0.f);
    fft64th<0>(s[r], tt, tws);
    float2* o = g_tmp + row * NX;
    o[tt] = s[r][tt]; o[tt + 64] = s[r][tt + 64];
}

template<int INV>
__device__ __forceinline__ void fft_col(float2 (*tile)[17], int tg, int tx, const float2* tws) {
    #pragma unroll
    for (int stage = 1; stage <= 7; stage++) {
        __syncthreads();
        int half = 1 << (stage - 1);
        #pragma unroll
        for (int m = 0; m < 8; m++) {
            int j  = tg + 8 * m;
            int p  = j & (half - 1);
            int i0 = ((j >> (stage - 1)) << stage) + p;
            int i1 = i0 + half;
            float2 w = tws[p << (7 - stage)];
            float wy = INV ? -w.y : w.y;
            float2 u = tile[i0][tx], v0 = tile[i1][tx];
            float2 v = make_float2(v0.x*w.x - v0.y*wy, v0.x*wy + v0.y*w.x);
            tile[i0][tx] = make_float2(u.x + v.x, u.y + v.y);
            tile[i1][tx] = make_float2(u.x - v.x, u.y - v.y);
        }
    }
}

// forward columns (launch 2): g_tmp -> g_alpha
__global__ void k_fft_cols_f() {
    __shared__ float2 tile[NY][17];
    __shared__ float2 tws[64];
    int t = threadIdx.x;
    make_tws(tws, t);
    int blk = blockIdx.x;
    int xt = blk & 7, img = blk >> 3;
    int x0 = xt * 16;
    int tg = t >> 4, tx = t & 15;
    const float2* base = g_tmp + (size_t)img * NY * NX + x0;
    #pragma unroll
    for (int c = 0; c < 16; c++) {
        int y = c * 8 + tg;
        tile[__brev(y) >> 25][tx] = base[(size_t)y * NX + tx];
    }
    fft_col<0>(tile, tg, tx, tws);
    __syncthreads();
    float2* ob = g_alpha + (size_t)img * NY * NX + x0;
    #pragma unroll
    for (int c = 0; c < 16; c++) {
        int y = c * 8 + tg;
        ob[(size_t)y * NX + tx] = tile[y][tx];
    }
}

// ---------------- T2: lane-wise two-accumulator complex GEMM (launch 3) -----
// accP = sum a*b = {Σax·bx, Σay·by}  -> re = lo - hi
// accQ = sum swap(a)*b = {Σay·bx, Σax·by} -> im = lo + hi
// b consumed raw from smem (no packs); one swap per a, reused over 5 kq.
#define T2_OT 64
#define T2_KC 40
#define T2_SMEM ((T2_OT*129 + T2_KC*129) * sizeof(float2))
extern __shared__ float2 t2sm[];
__global__ void __launch_bounds__(256, 2) k_T2() {
    float2* alphaS = t2sm;                   // [64 o][129 x]
    float2* a2S    = t2sm + T2_OT*129;       // [40 kq][129 x]
    const ull* alphaU = (const ull*)alphaS;
    const ull* a2U    = (const ull*)a2S;
    int blk = blockIdx.x;
    int oh = blk & 1;
    int bi = blk >> 1;
    int i  = bi & 31;
    int o0 = oh * T2_OT;
    int t  = threadIdx.x;
    const float2* A = g_alpha + (size_t)bi * NY * NX + (size_t)o0 * NX;
    #pragma unroll 4
    for (int l = t; l < T2_OT*128; l += 256) {
        int o = l >> 7, x = l & 127;
        alphaS[o*129 + x] = A[(size_t)o * NX + x];
    }
    int u = t >> 5, v = t & 31;
    #pragma unroll 1
    for (int c = 0; c < 4; c++) {
        int kq0 = c * T2_KC;
        __syncthreads();
        for (int l = t; l < T2_KC*128; l += 256) {
            int r = l >> 7, x = l & 127;
            a2S[r*129 + x] = g_A2[(size_t)(i*CO*M2 + kq0 + r) * NX + x];
        }
        __syncthreads();
        ull accP[5][2], accQ[5][2];
        #pragma unroll
        for (int j = 0; j < 5; j++)
            #pragma unroll
            for (int m = 0; m < 2; m++) {
                accP[j][m] = pack2(0.f, 0.f);
                accQ[j][m] = pack2(0.f, 0.f);
            }
        #pragma unroll 2
        for (int x = 0; x < 128; x++) {
            ull bv[5];
            #pragma unroll
            for (int j = 0; j < 5; j++)
                bv[j] = a2U[(u*5 + j)*129 + x];
            #pragma unroll
            for (int m = 0; m < 2; m++) {
                ull av  = alphaU[(v + 32*m)*129 + x];
                ull asw = swap2(av);
                #pragma unroll
                for (int j = 0; j < 5; j++) {
                    accP[j][m] = fma2(av,  bv[j], accP[j][m]);
                    accQ[j][m] = fma2(asw, bv[j], accQ[j][m]);
                }
            }
        }
        #pragma unroll
        for (int j = 0; j < 5; j++) {
            float2* dst = g_T2 + ((size_t)bi * CO*M2 + kq0 + u*5 + j) * NY + o0;
            #pragma unroll
            for (int m = 0; m < 2; m++) {
                float2 p = unpack2(accP[j][m]);
                float2 q = unpack2(accQ[j][m]);
                dst[v + 32*m] = make_float2(p.x - p.y, q.x + q.y);
            }
        }
    }
}

// ---------------- res2[b,k,p,q] = sum_i wr * sum_o A1[p,o]*T2[q,o] ---------
__global__ void k_res2(const float* __restrict__ wr_re, const float* __restrict__ wr_im) {
    int bk = blockIdx.x;
    int b = bk >> 5, k = bk & 31;
    int t = threadIdx.x;
    __shared__ float2 wrS[CI][M1*M2];
    for (int idx = t; idx < CI*M1*M2; idx += 128) {
        int i = idx / (M1*M2), pq = idx % (M1*M2);
        wrS[i][pq] = make_float2(wr_re[(i*CO + k)*M1*M2 + pq], wr_im[(i*CO + k)*M1*M2 + pq]);
    }
    __syncthreads();
    float2 acc[M1*M2];
    #pragma unroll
    for (int j = 0; j < M1*M2; j++) acc[j] = make_float2(0.f, 0.f);
    for (int i = 0; i < CI; i++) {
        float2 a1[M1], t2[M2];
        #pragma unroll
        for (int p = 0; p < M1; p++) a1[p] = g_A1[((i*CO + k)*M1 + p)*NY + t];
        #pragma unroll
        for (int q = 0; q < M2; q++) t2[q] = g_T2[(((size_t)(b*CI + i)*CO + k)*M2 + q)*NY + t];
        #pragma unroll
        for (int p = 0; p < M1; p++)
            #pragma unroll
            for (int q = 0; q < M2; q++) {
                float2 wa = cmul(wrS[i][p*M2 + q], a1[p]);
                acc[p*M2 + q] = cfma(wa, t2[q], acc[p*M2 + q]);
            }
    }
    #pragma unroll
    for (int j = 0; j < M1*M2; j++)
        #pragma unroll
        for (int off = 16; off; off >>= 1) {
            acc[j].x += __shfl_down_sync(0xffffffffu, acc[j].x, off);
            acc[j].y += __shfl_down_sync(0xffffffffu, acc[j].y, off);
        }
    __shared__ float2 red[4][M1*M2];
    int w = t >> 5, lane = t & 31;
    if (lane == 0) {
        #pragma unroll
        for (int j = 0; j < M1*M2; j++) red[w][j] = acc[j];
    }
    __syncthreads();
    if (t < M1*M2) {
        float2 s = red[0][t];
        #pragma unroll
        for (int w2 = 1; w2 < 4; w2++) { s.x += red[w2][t].x; s.y += red[w2][t].y; }
        g_res2[bk*M1*M2 + t] = s;
    }
}

// ---------------- G[b,c,k,q,z] = sum_p res2[b,c,p,q] * E1[c,k,p,z] ---------
__global__ void k_G() {
    int blk = blockIdx.x;
    int b = blk >> 10, c = (blk >> 5) & 31, k = blk & 31;
    int z = threadIdx.x;
    __shared__ float2 r2[M1*M2];
    if (z < M1*M2) r2[z] = g_res2[(b*CO + c)*M1*M2 + z];
    __syncthreads();
    float2 e1[M1];
    #pragma unroll
    for (int p = 0; p < M1; p++) e1[p] = g_E1[((c*CO + k)*M1 + p)*NY + z];
    #pragma unroll
    for (int q = 0; q < M2; q++) {
        float2 acc = make_float2(0.f, 0.f);
        #pragma unroll
        for (int p = 0; p < M1; p++) acc = cfma(r2[p*M2 + q], e1[p], acc);
        g_G[(((size_t)(b*CI + c)*CO + k)*M2 + q)*NY + z] = acc;
    }
}

// ---------------- Hsum full (streaming stores) ------------------------------
__global__ void k_hsum(const float* __restrict__ wr_re, const float* __restrict__ wr_im) {
    int ik = blockIdx.x;
    int t  = threadIdx.x;
    __shared__ float2 wrS[M1*M2];
    __shared__ float2 A1S[M1][NY];
    __shared__ float2 U[M2][NY];
    if (t < M1*M2) wrS[t] = make_float2(wr_re[ik*M1*M2 + t], wr_im[ik*M1*M2 + t]);
    #pragma unroll
    for (int p = 0; p < M1; p++) A1S[p][t] = g_A1[(ik*M1 + p)*NY + t];
    float2 a2[M2];
    #pragma unroll
    for (int q = 0; q < M2; q++) a2[q] = g_A2[(ik*M2 + q)*NX + t];
    __syncthreads();
    #pragma unroll
    for (int q = 0; q < M2; q++) {
        float2 acc = make_float2(0.f, 0.f);
        #pragma unroll
        for (int p = 0; p < M1; p++) acc = cfma(wrS[p*M2 + q], A1S[p][t], acc);
        U[q][t] = acc;
    }
    __syncthreads();
    float2* H = g_H + (size_t)ik * NY * NX;
    for (int o = 0; o < NY; o++) {
        float2 acc = make_float2(0.f, 0.f);
        #pragma unroll
        for (int q = 0; q < M2; q++) acc = cfma(U[q][o], a2[q], acc);
        __stcs(&H[o*NX + t], acc);
    }
}

// ---------------- res1 fused with inverse row FFT (full k range) ------------
__global__ void __launch_bounds__(128) k_res1f() {
    __shared__ float2 rows[32][129];
    __shared__ float2 tws[64];
    int o  = blockIdx.x & 127;
    int k0 = (blockIdx.x >> 7) * 4;
    int x  = threadIdx.x;
    make_tws(tws, x);
    ull acc[4][B];
    #pragma unroll
    for (int kk = 0; kk < 4; kk++)
        #pragma unroll
        for (int b = 0; b < B; b++) acc[kk][b] = pack2(0.f, 0.f);
    for (int i = 0; i < CI; i++) {
        ull hxx[4], hpm[4];
        #pragma unroll
        for (int kk = 0; kk < 4; kk++) {
            float2 h = __ldcs(&g_H[((size_t)(i*CO + k0 + kk) * NY + o) * NX + x]);
            hxx[kk] = pack2(h.x,  h.x);
            hpm[kk] = pack2(-h.y, h.y);
        }
        #pragma unroll
        for (int b = 0; b < B; b++) {
            float2 a = g_alpha[((size_t)(b*CI + i) * NY + o) * NX + x];
            ull au = pack2(a.x, a.y);
            ull as = pack2(a.y, a.x);
            #pragma unroll
            for (int kk = 0; kk < 4; kk++) {
                acc[kk][b] = fma2(au, hxx[kk], acc[kk][b]);
                acc[kk][b] = fma2(as, hpm[kk], acc[kk][b]);
            }
        }
    }
    int xr = __brev(x) >> 25;
    #pragma unroll
    for (int kk = 0; kk < 4; kk++)
        #pragma unroll
        for (int b = 0; b < B; b++)
            rows[kk*8 + b][xr] = unpack2(acc[kk][b]);
    __syncthreads();
    #pragma unroll
    for (int stage = 1; stage <= 7; stage++) {
        int half = 1 << (stage - 1);
        #pragma unroll
        for (int m = 0; m < 16; m++) {
            int l = x + 128*m;
            int r = l >> 6, j = l & 63;
            int p = j & (half - 1);
            int i0 = ((j >> (stage - 1)) << stage) + p;
            int i1 = i0 + half;
            float2 w = tws[p << (7 - stage)];
            float2 u = rows[r][i0], v0 = rows[r][i1];
            float2 v = make_float2(v0.x*w.x + v0.y*w.y, -v0.x*w.y + v0.y*w.x);
            rows[r][i0] = make_float2(u.x + v.x, u.y + v.y);
            rows[r][i1] = make_float2(u.x - v.x, u.y - v.y);
        }
        __syncthreads();
    }
    #pragma unroll
    for (int kk = 0; kk < 4; kk++)
        #pragma unroll
        for (int b = 0; b < B; b++)
            g_tmp[(((size_t)(b*CO + k0 + kk)) * NY + o) * NX + x] = rows[kk*8 + b][x];
}

// inverse columns + real part + scale: g_tmp -> out
__global__ void k_ifft_cols_r(float* __restrict__ out) {
    __shared__ float2 tile[NY][17];
    __shared__ float2 tws[64];
    int t = threadIdx.x;
    make_tws(tws, t);
    int blk = blockIdx.x;
    int xt = blk & 7, img = blk >> 3;
    int x0 = xt * 16;
    int tg = t >> 4, tx = t & 15;
    const float2* base = g_tmp + (size_t)img * NY * NX + x0;
    #pragma unroll
    for (int c = 0; c < 16; c++) {
        int y = c * 8 + tg;
        tile[__brev(y) >> 25][tx] = base[(size_t)y * NX + tx];
    }
    fft_col<1>(tile, tg, tx, tws);
    __syncthreads();
    const float INV = 1.0f / (float)(NY * NX);
    float* ob = out + (size_t)img * NY * NX + x0;
    #pragma unroll
    for (int c = 0; c < 16; c++) {
        int y = c * 8 + tg;
        ob[(size_t)y * NX + tx] = tile[y][tx].x * INV;
    }
}

// ---------------- x2: out += Re( G[z,cq] * E2[cq,x] ) / (NY*NX) ------------
__global__ void __launch_bounds__(256, 2) k_x2(float* __restrict__ out) {
    __shared__ float2 Gs[16][65];
    __shared__ float2 Es[16][129];
    int blk = blockIdx.x;
    int zh  = blk & 1;
    int bk  = blk >> 1;
    int b = bk >> 5, k = bk & 31;
    int z0 = zh * 64;
    int t = threadIdx.x;
    int u = t >> 5, v = t & 31;
    ull acc[8][4];
    #pragma unroll
    for (int j = 0; j < 8; j++)
        #pragma unroll
        for (int m = 0; m < 4; m++) acc[j][m] = pack2(0.f, 0.f);
    for (int k0 = 0; k0 < CI*M2; k0 += 16) {
        __syncthreads();
        for (int l = t; l < 16*64; l += 256) {
            int r = l >> 6, zz = l & 63;
            int cq = k0 + r; int c = cq / M2, q = cq % M2;
            Gs[r][zz] = g_G[(((size_t)(b*CI + c)*CO + k)*M2 + q)*NY + z0 + zz];
        }
        for (int l = t; l < 16*128; l += 256) {
            int r = l >> 7, xx = l & 127;
            int cq = k0 + r; int c = cq / M2, q = cq % M2;
            Es[r][xx] = g_E2[((size_t)(c*CO + k)*M2 + q)*NX + xx];
        }
        __syncthreads();
        #pragma unroll
        for (int kk = 0; kk < 16; kk++) {
            ull gpm[8];
            #pragma unroll
            for (int j = 0; j < 8; j++) {
                float2 g = Gs[kk][u*8 + j];
                gpm[j] = pack2(g.x, -g.y);
            }
            #pragma unroll
            for (int m = 0; m < 4; m++) {
                float2 e = Es[kk][v + 32*m];
                ull eu = pack2(e.x, e.y);
                #pragma unroll
                for (int j = 0; j < 8; j++)
                    acc[j][m] = fma2(eu, gpm[j], acc[j][m]);
            }
        }
    }
    const float INV = 1.0f / (float)(NY * NX);
    float* ob = out + (size_t)(b*CO + k) * NY * NX;
    #pragma unroll
    for (int j = 0; j < 8; j++) {
        int z = z0 + u*8 + j;
        #pragma unroll
        for (int m = 0; m < 4; m++) {
            float2 r = unpack2(acc[j][m]);
            ob[(size_t)z * NX + v + 32*m] += (r.x + r.y) * INV;
        }
    }
}

// ---------------------------------------------------------------------------
extern "C" void kernel_launch(void* const* d_in, const int* in_sizes, int n_in,
                              void* d_out, int out_size) {
    const float* x      = (const float*)d_in[0];
    const float* wp1_re = (const float*)d_in[1];
    const float* wp1_im = (const float*)d_in[2];
    const float* wp2_re = (const float*)d_in[3];
    const float* wp2_im = (const float*)d_in[4];
    const float* wr_re  = (const float*)d_in[5];
    const float* wr_im  = (const float*)d_in[6];
    const float* ty     = (const float*)d_in[7];
    const float* tx     = (const float*)d_in[8];
    float* out = (float*)d_out;

    cudaFuncSetAttribute(k_T2, cudaFuncAttributeMaxDynamicSharedMemorySize, (int)T2_SMEM);

    k_fac         <<<CI*CO*(M1+M2), 128>>>(wp1_re, wp1_im, wp2_re, wp2_im, ty, tx);  // 0
    k_fft_rows_f  <<<B*CI*NY/2, 128>>>(x);                                           // 1
    k_fft_cols_f  <<<B*CI*8, 128>>>();                                               // 2
    k_T2          <<<B*CI*2, 256, T2_SMEM>>>();                                      // 3 (profiled)
    k_res2        <<<B*CO, 128>>>(wr_re, wr_im);                                     // 4
    k_G           <<<B*CI*CO, 128>>>();                                              // 5
    k_hsum        <<<CI*CO, 128>>>(wr_re, wr_im);                                    // 6
    k_res1f       <<<8*NY, 128>>>();                                                 // 7
    k_ifft_cols_r <<<B*CO*8, 128>>>(out);                                            // 8
    k_x2          <<<B*CO*2, 256>>>(out);                                            // 9
}